// round 1
// baseline (speedup 1.0000x reference)
#include <cuda_runtime.h>
#include <math.h>

#define DOF 7
#define BATCH 16384
#define NTHREADS 64
#define ACTION_RANGE 50.0f
#define MAX_VEL 20.0f
#define TSTEP 0.1f

struct Params {
    float w[DOF][3];      // normalized screw angular part
    float v[DOF][3];      // screw linear part
    float wxv[DOF][3];    // w x v
    float wdv[DOF];       // w . v
    float Rm[DOF][9];     // trans_inv(Mlist[i]) rotation  (= R_i^T), row-major
    float pm[DOF][3];     // trans_inv(Mlist[i]) translation (= -R_i^T p_i)
    float Gd[DOF][6];     // diagonal spatial inertia
    float Rend[9];        // adjoint(trans_inv(Mlist[7])): rotation block
    float Qend[9];        // hat(p') * Rend
    float Mr[DOF + 1][9]; // Mlist rotations (for FK)
    float Mp[DOF + 1][3]; // Mlist translations (for FK)
};

__device__ Params g_params;

__device__ __forceinline__ void cross3(const float* a, const float* b, float* o) {
    o[0] = a[1] * b[2] - a[2] * b[1];
    o[1] = a[2] * b[0] - a[0] * b[2];
    o[2] = a[0] * b[1] - a[1] * b[0];
}

// ---------------------------------------------------------------------------
// Setup: build all batch-invariant quantities once.
// ---------------------------------------------------------------------------
__global__ void setup_kernel(const float* __restrict__ M_,
                             const float* __restrict__ A_,
                             const float* __restrict__ G_) {
    if (threadIdx.x != 0 || blockIdx.x != 0) return;
    Params* P = &g_params;

    for (int m = 0; m <= DOF; m++) {
        const float* M = M_ + m * 16;
        float a1[3], a2[3], p[3];
        for (int r = 0; r < 3; r++) { a1[r] = M[r * 4 + 0]; a2[r] = M[r * 4 + 1]; p[r] = M[r * 4 + 3]; }
        float n1 = sqrtf(a1[0] * a1[0] + a1[1] * a1[1] + a1[2] * a1[2]);
        float b1[3] = { a1[0] / n1, a1[1] / n1, a1[2] / n1 };
        float d = a2[0] * b1[0] + a2[1] * b1[1] + a2[2] * b1[2];
        float a2o[3] = { a2[0] - d * b1[0], a2[1] - d * b1[1], a2[2] - d * b1[2] };
        float n2 = sqrtf(a2o[0] * a2o[0] + a2o[1] * a2o[1] + a2o[2] * a2o[2]);
        float b2[3] = { a2o[0] / n2, a2o[1] / n2, a2o[2] / n2 };
        float b3[3]; cross3(b1, b2, b3);
        float R[9];
        for (int r = 0; r < 3; r++) { R[r * 3 + 0] = b1[r]; R[r * 3 + 1] = b2[r]; R[r * 3 + 2] = b3[r]; }
        for (int k = 0; k < 9; k++) P->Mr[m][k] = R[k];
        for (int r = 0; r < 3; r++) P->Mp[m][r] = p[r];

        float Rt_[9];
        for (int r = 0; r < 3; r++)
            for (int c = 0; c < 3; c++) Rt_[r * 3 + c] = R[c * 3 + r];
        float pmv[3];
        for (int r = 0; r < 3; r++)
            pmv[r] = -(Rt_[r * 3 + 0] * p[0] + Rt_[r * 3 + 1] * p[1] + Rt_[r * 3 + 2] * p[2]);

        if (m < DOF) {
            for (int k = 0; k < 9; k++) P->Rm[m][k] = Rt_[k];
            for (int r = 0; r < 3; r++) P->pm[m][r] = pmv[r];
        } else {
            for (int k = 0; k < 9; k++) P->Rend[k] = Rt_[k];
            for (int c = 0; c < 3; c++) {
                P->Qend[0 * 3 + c] = -pmv[2] * Rt_[1 * 3 + c] + pmv[1] * Rt_[2 * 3 + c];
                P->Qend[1 * 3 + c] =  pmv[2] * Rt_[0 * 3 + c] - pmv[0] * Rt_[2 * 3 + c];
                P->Qend[2 * 3 + c] = -pmv[1] * Rt_[0 * 3 + c] + pmv[0] * Rt_[1 * 3 + c];
            }
        }
    }

    for (int j = 0; j < DOF; j++) {
        const float* a = A_ + j * 6;
        float nw = sqrtf(a[0] * a[0] + a[1] * a[1] + a[2] * a[2]);
        float w[3] = { a[0] / nw, a[1] / nw, a[2] / nw };
        float v[3] = { a[3], a[4], a[5] };
        for (int k = 0; k < 3; k++) { P->w[j][k] = w[k]; P->v[j][k] = v[k]; }
        cross3(w, v, P->wxv[j]);
        P->wdv[j] = w[0] * v[0] + w[1] * v[1] + w[2] * v[2];
        float g0 = fabsf(G_[j * 4 + 0]);
        float g1 = fabsf(G_[j * 4 + 1]);
        float g2 = fabsf(G_[j * 4 + 2]);
        float g3 = fabsf(G_[j * 4 + 3]);
        P->Gd[j][0] = g0; P->Gd[j][1] = g1; P->Gd[j][2] = g2;
        P->Gd[j][3] = g3; P->Gd[j][4] = g3; P->Gd[j][5] = g3;
    }
}

// AdT @ V : in = (w,v), out = (R w, Q w + R v)
__device__ __forceinline__ void adV_apply(const float* R, const float* Q,
                                          const float* in, float* out) {
#pragma unroll
    for (int r = 0; r < 3; r++) {
        out[r]     = R[r * 3 + 0] * in[0] + R[r * 3 + 1] * in[1] + R[r * 3 + 2] * in[2];
        out[3 + r] = Q[r * 3 + 0] * in[0] + Q[r * 3 + 1] * in[1] + Q[r * 3 + 2] * in[2]
                   + R[r * 3 + 0] * in[3] + R[r * 3 + 1] * in[4] + R[r * 3 + 2] * in[5];
    }
}

// AdT^T @ F : in = (m,f), out = (R^T m + Q^T f, R^T f)
__device__ __forceinline__ void adTF_apply(const float* R, const float* Q,
                                           const float* in, float* out) {
#pragma unroll
    for (int r = 0; r < 3; r++) {
        out[r]     = R[0 * 3 + r] * in[0] + R[1 * 3 + r] * in[1] + R[2 * 3 + r] * in[2]
                   + Q[0 * 3 + r] * in[3] + Q[1 * 3 + r] * in[4] + Q[2 * 3 + r] * in[5];
        out[3 + r] = R[0 * 3 + r] * in[3] + R[1 * 3 + r] * in[4] + R[2 * 3 + r] * in[5];
    }
}

// One forward-dynamics evaluation: qacc = M(q)^-1 (tau - bias(q,dq))
__device__ __forceinline__ void compute_qacc(const Params& P, const float* q,
                                             const float* dq, const float* tq,
                                             const float* g, float* qacc) {
    float Rt[DOF][9], Qm[DOF][9];

    // Build per-joint adjoints AdT_i = adjoint(exp(-q_i A_i) * Minv_i)
#pragma unroll
    for (int i = 0; i < DOF; i++) {
        float s, c;
        sincosf(q[i], &s, &c);
        float th = -q[i], se = -s;
        const float* w = P.w[i];
        const float* v = P.v[i];
        float omc = 1.0f - c;
        float Re[9];
        Re[0] = c + omc * w[0] * w[0];
        Re[1] = se * (-w[2]) + omc * w[0] * w[1];
        Re[2] = se * ( w[1]) + omc * w[0] * w[2];
        Re[3] = se * ( w[2]) + omc * w[1] * w[0];
        Re[4] = c + omc * w[1] * w[1];
        Re[5] = se * (-w[0]) + omc * w[1] * w[2];
        Re[6] = se * (-w[1]) + omc * w[2] * w[0];
        Re[7] = se * ( w[0]) + omc * w[2] * w[1];
        Re[8] = c + omc * w[2] * w[2];
        float tms = th - se;
        float pe[3];
#pragma unroll
        for (int k = 0; k < 3; k++)
            pe[k] = th * v[k] + omc * P.wxv[i][k] + tms * (w[k] * P.wdv[i] - v[k]);
        const float* Rm = P.Rm[i];
        float* R = Rt[i];
#pragma unroll
        for (int r = 0; r < 3; r++)
#pragma unroll
            for (int cc = 0; cc < 3; cc++)
                R[r * 3 + cc] = Re[r * 3 + 0] * Rm[0 * 3 + cc]
                              + Re[r * 3 + 1] * Rm[1 * 3 + cc]
                              + Re[r * 3 + 2] * Rm[2 * 3 + cc];
        float pt[3];
#pragma unroll
        for (int r = 0; r < 3; r++)
            pt[r] = Re[r * 3 + 0] * P.pm[i][0] + Re[r * 3 + 1] * P.pm[i][1]
                  + Re[r * 3 + 2] * P.pm[i][2] + pe[r];
        float* Q = Qm[i];
#pragma unroll
        for (int cc = 0; cc < 3; cc++) {
            Q[0 * 3 + cc] = -pt[2] * R[1 * 3 + cc] + pt[1] * R[2 * 3 + cc];
            Q[1 * 3 + cc] =  pt[2] * R[0 * 3 + cc] - pt[0] * R[2 * 3 + cc];
            Q[2 * 3 + cc] = -pt[1] * R[0 * 3 + cc] + pt[0] * R[1 * 3 + cc];
        }
    }

    // ---- bias inverse dynamics (ddq = 0, with gravity + velocity) ----
    float Vs[DOF][6], Vds[DOF][6];
    {
        float V[6] = { 0, 0, 0, 0, 0, 0 };
        float Vd[6] = { 0, 0, 0, -g[0], -g[1], -g[2] };
#pragma unroll
        for (int i = 0; i < DOF; i++) {
            float t[6];
            adV_apply(Rt[i], Qm[i], V, t);
#pragma unroll
            for (int k = 0; k < 3; k++) {
                V[k]     = t[k]     + P.w[i][k] * dq[i];
                V[3 + k] = t[3 + k] + P.v[i][k] * dq[i];
            }
            float t2[6];
            adV_apply(Rt[i], Qm[i], Vd, t2);
            float aw[3], av1[3], av2[3];
            cross3(&V[0], P.w[i], aw);   // Vw x w
            cross3(&V[3], P.w[i], av1);  // Vv x w
            cross3(&V[0], P.v[i], av2);  // Vw x v
#pragma unroll
            for (int k = 0; k < 3; k++) {
                Vd[k]     = t2[k]     + aw[k] * dq[i];
                Vd[3 + k] = t2[3 + k] + (av1[k] + av2[k]) * dq[i];
            }
#pragma unroll
            for (int k = 0; k < 6; k++) { Vs[i][k] = V[k]; Vds[i][k] = Vd[k]; }
        }
    }
    float bias[DOF];
    {
        float F[6] = { 0, 0, 0, 0, 0, 0 };
#pragma unroll
        for (int ii = DOF - 1; ii >= 0; ii--) {
            float X[6];
            if (ii == DOF - 1) adTF_apply(P.Rend, P.Qend, F, X);
            else               adTF_apply(Rt[ii + 1], Qm[ii + 1], F, X);
            float GV[6], GVd[6];
#pragma unroll
            for (int k = 0; k < 6; k++) {
                GV[k]  = P.Gd[ii][k] * Vs[ii][k];
                GVd[k] = P.Gd[ii][k] * Vds[ii][k];
            }
            float c1[3], c2[3], c3[3];
            cross3(&Vs[ii][0], &GV[0], c1); // Vw x GVm
            cross3(&Vs[ii][3], &GV[3], c2); // Vv x GVf
            cross3(&Vs[ii][0], &GV[3], c3); // Vw x GVf
#pragma unroll
            for (int k = 0; k < 3; k++) {
                F[k]     = X[k]     + GVd[k]     + c1[k] + c2[k];
                F[3 + k] = X[3 + k] + GVd[3 + k] + c3[k];
            }
            bias[ii] = F[0] * P.w[ii][0] + F[1] * P.w[ii][1] + F[2] * P.w[ii][2]
                     + F[3] * P.v[ii][0] + F[4] * P.v[ii][1] + F[5] * P.v[ii][2];
        }
    }

    // ---- mass matrix: column j = ID(q, 0, e_j, g=0) ; V == 0 everywhere ----
    float Mm[DOF][DOF];
#pragma unroll
    for (int j = 0; j < DOF; j++) {
        float vd[DOF][6];
#pragma unroll
        for (int k = 0; k < 3; k++) { vd[j][k] = P.w[j][k]; vd[j][3 + k] = P.v[j][k]; }
#pragma unroll
        for (int i = j + 1; i < DOF; i++) adV_apply(Rt[i], Qm[i], vd[i - 1], vd[i]);
        float F[6] = { 0, 0, 0, 0, 0, 0 };
#pragma unroll
        for (int ii = DOF - 1; ii >= 0; ii--) {
            float X[6];
            if (ii == DOF - 1) adTF_apply(P.Rend, P.Qend, F, X);
            else               adTF_apply(Rt[ii + 1], Qm[ii + 1], F, X);
            if (ii >= j) {
#pragma unroll
                for (int k = 0; k < 6; k++) F[k] = X[k] + P.Gd[ii][k] * vd[ii][k];
            } else {
#pragma unroll
                for (int k = 0; k < 6; k++) F[k] = X[k];
            }
            Mm[ii][j] = F[0] * P.w[ii][0] + F[1] * P.w[ii][1] + F[2] * P.w[ii][2]
                      + F[3] * P.v[ii][0] + F[4] * P.v[ii][1] + F[5] * P.v[ii][2];
        }
    }

    // ---- solve M qacc = tau - bias (LU, no pivoting: M is SPD) ----
    float x[DOF];
#pragma unroll
    for (int i = 0; i < DOF; i++) x[i] = tq[i] - bias[i];
#pragma unroll
    for (int k = 0; k < DOF; k++) {
        float inv = 1.0f / Mm[k][k];
#pragma unroll
        for (int i = k + 1; i < DOF; i++) {
            float f = Mm[i][k] * inv;
#pragma unroll
            for (int jj = k + 1; jj < DOF; jj++) Mm[i][jj] -= f * Mm[k][jj];
            x[i] -= f * x[k];
        }
    }
#pragma unroll
    for (int i = DOF - 1; i >= 0; i--) {
        float s = x[i];
#pragma unroll
        for (int jj = i + 1; jj < DOF; jj++) s -= Mm[i][jj] * qacc[jj];
        qacc[i] = s / Mm[i][i];
    }
}

// ---------------------------------------------------------------------------
// Main kernel: one thread per batch element; RK4 + wrap/clip + FK.
// ---------------------------------------------------------------------------
__global__ void __launch_bounds__(NTHREADS)
arm_kernel(const float* __restrict__ state, const float* __restrict__ action,
           const float* __restrict__ gravity, float* __restrict__ out) {
    __shared__ Params sp;
    {
        const float* src = reinterpret_cast<const float*>(&g_params);
        float* dst = reinterpret_cast<float*>(&sp);
        for (int idx = threadIdx.x; idx < (int)(sizeof(Params) / 4); idx += NTHREADS)
            dst[idx] = src[idx];
    }
    __syncthreads();

    int b = blockIdx.x * NTHREADS + threadIdx.x;
    if (b >= BATCH) return;

    float q0[DOF], dq0[DOF], tq[DOF], g[3];
#pragma unroll
    for (int i = 0; i < DOF; i++) {
        q0[i]  = state[b * 14 + i];
        dq0[i] = state[b * 14 + DOF + i];
        tq[i]  = action[b * DOF + i] * ACTION_RANGE;
    }
    g[0] = gravity[0]; g[1] = gravity[1]; g[2] = gravity[2];

    const float h = TSTEP;
    float qs[DOF], dqs[DOF], qc[DOF], dqc[DOF];
#pragma unroll
    for (int i = 0; i < DOF; i++) { qc[i] = q0[i]; dqc[i] = dq0[i]; qs[i] = 0.f; dqs[i] = 0.f; }

#pragma unroll 1
    for (int st = 0; st < 4; st++) {
        float qacc[DOF];
        compute_qacc(sp, qc, dqc, tq, g, qacc);
        float wk = (st == 1 || st == 2) ? 2.0f : 1.0f;
        float cc = (st == 2) ? 1.0f : 0.5f;
#pragma unroll
        for (int i = 0; i < DOF; i++) {
            qs[i]  += wk * dqc[i];
            dqs[i] += wk * qacc[i];
            qc[i]  = q0[i]  + cc * h * dqc[i];
            dqc[i] = dq0[i] + cc * h * qacc[i];
        }
    }

    const float PI = 3.14159265358979323846f;
    const float TWO_PI = 6.28318530717958647692f;
    float qn[DOF];
#pragma unroll
    for (int i = 0; i < DOF; i++) {
        float qv = q0[i] + (h / 6.0f) * qs[i];
        float t = fmodf(qv + PI, TWO_PI);
        if (t < 0.0f) t += TWO_PI;
        qn[i] = t - PI;
        float dv = dq0[i] + (h / 6.0f) * dqs[i];
        dv = fminf(fmaxf(dv, -MAX_VEL), MAX_VEL);
        out[b * 14 + i] = qn[i];
        out[b * 14 + DOF + i] = dv;
    }

    // ---- FK: end-effector (x, y) ----
    float TR[9] = { 1, 0, 0, 0, 1, 0, 0, 0, 1 };
    float Tp[3] = { 0, 0, 0 };
#pragma unroll
    for (int i = 0; i < DOF; i++) {
        float s, c;
        sincosf(qn[i], &s, &c);
        const float* w = sp.w[i];
        const float* v = sp.v[i];
        float omc = 1.0f - c;
        float Re[9];
        Re[0] = c + omc * w[0] * w[0];
        Re[1] = s * (-w[2]) + omc * w[0] * w[1];
        Re[2] = s * ( w[1]) + omc * w[0] * w[2];
        Re[3] = s * ( w[2]) + omc * w[1] * w[0];
        Re[4] = c + omc * w[1] * w[1];
        Re[5] = s * (-w[0]) + omc * w[1] * w[2];
        Re[6] = s * (-w[1]) + omc * w[2] * w[0];
        Re[7] = s * ( w[0]) + omc * w[2] * w[1];
        Re[8] = c + omc * w[2] * w[2];
        float th = qn[i];
        float tms = th - s;
        float pe[3];
#pragma unroll
        for (int k = 0; k < 3; k++)
            pe[k] = th * v[k] + omc * sp.wxv[i][k] + tms * (w[k] * sp.wdv[i] - v[k]);
        // X = M_i * E_i
        const float* Mr = sp.Mr[i];
        float Rx[9], px[3];
#pragma unroll
        for (int r = 0; r < 3; r++) {
#pragma unroll
            for (int cc = 0; cc < 3; cc++)
                Rx[r * 3 + cc] = Mr[r * 3 + 0] * Re[0 * 3 + cc]
                               + Mr[r * 3 + 1] * Re[1 * 3 + cc]
                               + Mr[r * 3 + 2] * Re[2 * 3 + cc];
            px[r] = Mr[r * 3 + 0] * pe[0] + Mr[r * 3 + 1] * pe[1] + Mr[r * 3 + 2] * pe[2]
                  + sp.Mp[i][r];
        }
        // T = T * X
        float nR[9], nP[3];
#pragma unroll
        for (int r = 0; r < 3; r++) {
#pragma unroll
            for (int cc = 0; cc < 3; cc++)
                nR[r * 3 + cc] = TR[r * 3 + 0] * Rx[0 * 3 + cc]
                               + TR[r * 3 + 1] * Rx[1 * 3 + cc]
                               + TR[r * 3 + 2] * Rx[2 * 3 + cc];
            nP[r] = TR[r * 3 + 0] * px[0] + TR[r * 3 + 1] * px[1] + TR[r * 3 + 2] * px[2] + Tp[r];
        }
#pragma unroll
        for (int k = 0; k < 9; k++) TR[k] = nR[k];
#pragma unroll
        for (int k = 0; k < 3; k++) Tp[k] = nP[k];
    }
    const float* Mp7 = sp.Mp[DOF];
    float ex = TR[0] * Mp7[0] + TR[1] * Mp7[1] + TR[2] * Mp7[2] + Tp[0];
    float ey = TR[3] * Mp7[0] + TR[4] * Mp7[1] + TR[5] * Mp7[2] + Tp[1];
    out[BATCH * 14 + b * 2 + 0] = ex;
    out[BATCH * 14 + b * 2 + 1] = ey;
}

extern "C" void kernel_launch(void* const* d_in, const int* in_sizes, int n_in,
                              void* d_out, int out_size) {
    const float* state   = (const float*)d_in[0];
    const float* action  = (const float*)d_in[1];
    const float* M_      = (const float*)d_in[2];
    const float* A_      = (const float*)d_in[3];
    const float* G_      = (const float*)d_in[4];
    const float* gravity = (const float*)d_in[5];
    float* out = (float*)d_out;

    setup_kernel<<<1, 32>>>(M_, A_, G_);
    arm_kernel<<<(BATCH + NTHREADS - 1) / NTHREADS, NTHREADS>>>(state, action, gravity, out);
}

// round 2
// speedup vs baseline: 1.3405x; 1.3405x over previous
#include <cuda_runtime.h>
#include <math.h>

#define DOF 7
#define BATCH 16384
#define NTHREADS 32
#define ACTION_RANGE 50.0f
#define MAX_VEL 20.0f
#define TSTEP 0.1f

struct Params {
    float w[DOF][3];      // normalized screw angular part
    float v[DOF][3];      // screw linear part
    float wxv[DOF][3];    // w x v
    float wdv[DOF];       // w . v
    float Rm[DOF][9];     // trans_inv(Mlist[i]) rotation (= R_i^T)
    float pm[DOF][3];     // trans_inv(Mlist[i]) translation
    float Gd[DOF][6];     // diagonal spatial inertia
    float Rend[9];        // trans_inv(Mlist[7]) rotation
    float pend[3];        // trans_inv(Mlist[7]) translation
    float Mr[DOF + 1][9]; // Mlist rotations (for FK)
    float Mp[DOF + 1][3]; // Mlist translations (for FK)
};

__device__ Params g_params;

__device__ __forceinline__ void cross3(const float* a, const float* b, float* o) {
    o[0] = a[1] * b[2] - a[2] * b[1];
    o[1] = a[2] * b[0] - a[0] * b[2];
    o[2] = a[0] * b[1] - a[1] * b[0];
}

// ---------------------------------------------------------------------------
// Setup: build all batch-invariant quantities once.
// ---------------------------------------------------------------------------
__global__ void setup_kernel(const float* __restrict__ M_,
                             const float* __restrict__ A_,
                             const float* __restrict__ G_) {
    if (threadIdx.x != 0 || blockIdx.x != 0) return;
    Params* P = &g_params;

    for (int m = 0; m <= DOF; m++) {
        const float* M = M_ + m * 16;
        float a1[3], a2[3], p[3];
        for (int r = 0; r < 3; r++) { a1[r] = M[r * 4 + 0]; a2[r] = M[r * 4 + 1]; p[r] = M[r * 4 + 3]; }
        float n1 = sqrtf(a1[0] * a1[0] + a1[1] * a1[1] + a1[2] * a1[2]);
        float b1[3] = { a1[0] / n1, a1[1] / n1, a1[2] / n1 };
        float d = a2[0] * b1[0] + a2[1] * b1[1] + a2[2] * b1[2];
        float a2o[3] = { a2[0] - d * b1[0], a2[1] - d * b1[1], a2[2] - d * b1[2] };
        float n2 = sqrtf(a2o[0] * a2o[0] + a2o[1] * a2o[1] + a2o[2] * a2o[2]);
        float b2[3] = { a2o[0] / n2, a2o[1] / n2, a2o[2] / n2 };
        float b3[3]; cross3(b1, b2, b3);
        float R[9];
        for (int r = 0; r < 3; r++) { R[r * 3 + 0] = b1[r]; R[r * 3 + 1] = b2[r]; R[r * 3 + 2] = b3[r]; }
        for (int k = 0; k < 9; k++) P->Mr[m][k] = R[k];
        for (int r = 0; r < 3; r++) P->Mp[m][r] = p[r];

        float Rt_[9];
        for (int r = 0; r < 3; r++)
            for (int c = 0; c < 3; c++) Rt_[r * 3 + c] = R[c * 3 + r];
        float pmv[3];
        for (int r = 0; r < 3; r++)
            pmv[r] = -(Rt_[r * 3 + 0] * p[0] + Rt_[r * 3 + 1] * p[1] + Rt_[r * 3 + 2] * p[2]);

        if (m < DOF) {
            for (int k = 0; k < 9; k++) P->Rm[m][k] = Rt_[k];
            for (int r = 0; r < 3; r++) P->pm[m][r] = pmv[r];
        } else {
            for (int k = 0; k < 9; k++) P->Rend[k] = Rt_[k];
            for (int r = 0; r < 3; r++) P->pend[r] = pmv[r];
        }
    }

    for (int j = 0; j < DOF; j++) {
        const float* a = A_ + j * 6;
        float nw = sqrtf(a[0] * a[0] + a[1] * a[1] + a[2] * a[2]);
        float w[3] = { a[0] / nw, a[1] / nw, a[2] / nw };
        float v[3] = { a[3], a[4], a[5] };
        for (int k = 0; k < 3; k++) { P->w[j][k] = w[k]; P->v[j][k] = v[k]; }
        cross3(w, v, P->wxv[j]);
        P->wdv[j] = w[0] * v[0] + w[1] * v[1] + w[2] * v[2];
        float g0 = fabsf(G_[j * 4 + 0]);
        float g1 = fabsf(G_[j * 4 + 1]);
        float g2 = fabsf(G_[j * 4 + 2]);
        float g3 = fabsf(G_[j * 4 + 3]);
        P->Gd[j][0] = g0; P->Gd[j][1] = g1; P->Gd[j][2] = g2;
        P->Gd[j][3] = g3; P->Gd[j][4] = g3; P->Gd[j][5] = g3;
    }
}

// AdT @ V with compact (R, p) repr: out_w = R w_in ; out_v = p x out_w + R v_in
__device__ __forceinline__ void adV(const float* __restrict__ R, const float* __restrict__ p,
                                    const float* __restrict__ in, float* __restrict__ out) {
    float a0 = R[0] * in[0] + R[1] * in[1] + R[2] * in[2];
    float a1 = R[3] * in[0] + R[4] * in[1] + R[5] * in[2];
    float a2 = R[6] * in[0] + R[7] * in[1] + R[8] * in[2];
    float b0 = R[0] * in[3] + R[1] * in[4] + R[2] * in[5];
    float b1 = R[3] * in[3] + R[4] * in[4] + R[5] * in[5];
    float b2 = R[6] * in[3] + R[7] * in[4] + R[8] * in[5];
    out[0] = a0; out[1] = a1; out[2] = a2;
    out[3] = b0 + p[1] * a2 - p[2] * a1;
    out[4] = b1 + p[2] * a0 - p[0] * a2;
    out[5] = b2 + p[0] * a1 - p[1] * a0;
}

// AdT^T @ F with compact (R, p): out_m = R^T (m + f x p) ; out_f = R^T f
__device__ __forceinline__ void adTF(const float* __restrict__ R, const float* __restrict__ p,
                                     const float* __restrict__ in, float* __restrict__ out) {
    float c0 = in[4] * p[2] - in[5] * p[1];
    float c1 = in[5] * p[0] - in[3] * p[2];
    float c2 = in[3] * p[1] - in[4] * p[0];
    float m0 = in[0] + c0, m1 = in[1] + c1, m2 = in[2] + c2;
    out[0] = R[0] * m0 + R[3] * m1 + R[6] * m2;
    out[1] = R[1] * m0 + R[4] * m1 + R[7] * m2;
    out[2] = R[2] * m0 + R[5] * m1 + R[8] * m2;
    out[3] = R[0] * in[3] + R[3] * in[4] + R[6] * in[5];
    out[4] = R[1] * in[3] + R[4] * in[4] + R[7] * in[5];
    out[5] = R[2] * in[3] + R[5] * in[4] + R[8] * in[5];
}

#define MTRI(i, j) Mtri[((i) * ((i) + 1)) / 2 + (j)]   // i >= j

// One forward-dynamics evaluation: qacc = M(q)^-1 (tau - bias(q,dq))
__device__ __forceinline__ void compute_qacc(const Params& P, const float* q,
                                             const float* dq, const float* tq,
                                             const float* g, float* qacc) {
    float Rj[DOF][9], Pj[DOF][3];

    // Per-joint adjoints AdT_i = adjoint(exp(-q_i A_i) * Minv_i), stored as (R, p)
#pragma unroll
    for (int i = 0; i < DOF; i++) {
        float s, c;
        __sincosf(q[i], &s, &c);
        float th = -q[i], se = -s;
        const float* w = P.w[i];
        const float* v = P.v[i];
        float omc = 1.0f - c;
        float Re[9];
        Re[0] = c + omc * w[0] * w[0];
        Re[1] = se * (-w[2]) + omc * w[0] * w[1];
        Re[2] = se * ( w[1]) + omc * w[0] * w[2];
        Re[3] = se * ( w[2]) + omc * w[1] * w[0];
        Re[4] = c + omc * w[1] * w[1];
        Re[5] = se * (-w[0]) + omc * w[1] * w[2];
        Re[6] = se * (-w[1]) + omc * w[2] * w[0];
        Re[7] = se * ( w[0]) + omc * w[2] * w[1];
        Re[8] = c + omc * w[2] * w[2];
        float tms = th - se;
        float pe[3];
#pragma unroll
        for (int k = 0; k < 3; k++)
            pe[k] = th * v[k] + omc * P.wxv[i][k] + tms * (w[k] * P.wdv[i] - v[k]);
        const float* Rm = P.Rm[i];
        float* R = Rj[i];
#pragma unroll
        for (int r = 0; r < 3; r++)
#pragma unroll
            for (int cc = 0; cc < 3; cc++)
                R[r * 3 + cc] = Re[r * 3 + 0] * Rm[0 * 3 + cc]
                              + Re[r * 3 + 1] * Rm[1 * 3 + cc]
                              + Re[r * 3 + 2] * Rm[2 * 3 + cc];
#pragma unroll
        for (int r = 0; r < 3; r++)
            Pj[i][r] = Re[r * 3 + 0] * P.pm[i][0] + Re[r * 3 + 1] * P.pm[i][1]
                     + Re[r * 3 + 2] * P.pm[i][2] + pe[r];
    }

    // ---- bias forward sweep; store per-joint wrench contribution fb[i] ----
    float fb[DOF][6];
    {
        float V[6] = { 0, 0, 0, 0, 0, 0 };
        float Vd[6] = { 0, 0, 0, -g[0], -g[1], -g[2] };
#pragma unroll
        for (int i = 0; i < DOF; i++) {
            float t[6];
            adV(Rj[i], Pj[i], V, t);
#pragma unroll
            for (int k = 0; k < 3; k++) {
                V[k]     = t[k]     + P.w[i][k] * dq[i];
                V[3 + k] = t[3 + k] + P.v[i][k] * dq[i];
            }
            float t2[6];
            adV(Rj[i], Pj[i], Vd, t2);
            float aw[3], av1[3], av2[3];
            cross3(&V[0], P.w[i], aw);
            cross3(&V[3], P.w[i], av1);
            cross3(&V[0], P.v[i], av2);
#pragma unroll
            for (int k = 0; k < 3; k++) {
                Vd[k]     = t2[k]     + aw[k] * dq[i];
                Vd[3 + k] = t2[3 + k] + (av1[k] + av2[k]) * dq[i];
            }
            float GV[6], GVd[6];
#pragma unroll
            for (int k = 0; k < 6; k++) {
                GV[k]  = P.Gd[i][k] * V[k];
                GVd[k] = P.Gd[i][k] * Vd[k];
            }
            float c1[3], c2[3], c3[3];
            cross3(&V[0], &GV[0], c1);
            cross3(&V[3], &GV[3], c2);
            cross3(&V[0], &GV[3], c3);
#pragma unroll
            for (int k = 0; k < 3; k++) {
                fb[i][k]     = GVd[k]     + c1[k] + c2[k];
                fb[i][3 + k] = GVd[3 + k] + c3[k];
            }
        }
    }

    // ---- bias backward sweep (ftip = 0 => end adjoint contributes nothing) ----
    float bias[DOF];
    {
        float F[6];
#pragma unroll
        for (int k = 0; k < 6; k++) F[k] = fb[DOF - 1][k];
        bias[DOF - 1] = F[0] * P.w[DOF - 1][0] + F[1] * P.w[DOF - 1][1] + F[2] * P.w[DOF - 1][2]
                      + F[3] * P.v[DOF - 1][0] + F[4] * P.v[DOF - 1][1] + F[5] * P.v[DOF - 1][2];
#pragma unroll
        for (int ii = DOF - 2; ii >= 0; ii--) {
            float X[6];
            adTF(Rj[ii + 1], Pj[ii + 1], F, X);
#pragma unroll
            for (int k = 0; k < 6; k++) F[k] = X[k] + fb[ii][k];
            bias[ii] = F[0] * P.w[ii][0] + F[1] * P.w[ii][1] + F[2] * P.w[ii][2]
                     + F[3] * P.v[ii][0] + F[4] * P.v[ii][1] + F[5] * P.v[ii][2];
        }
    }

    // ---- mass matrix: lower triangle only (M is symmetric). Column j:
    //      ID with ddq=e_j, V=0, g=0, truncated at row j. ----
    float Mtri[(DOF * (DOF + 1)) / 2];
#pragma unroll
    for (int j = 0; j < DOF; j++) {
        float vd[DOF][6];
#pragma unroll
        for (int k = 0; k < 3; k++) { vd[j][k] = P.w[j][k]; vd[j][3 + k] = P.v[j][k]; }
#pragma unroll
        for (int i = j + 1; i < DOF; i++) adV(Rj[i], Pj[i], vd[i - 1], vd[i]);
        float F[6];
#pragma unroll
        for (int k = 0; k < 6; k++) F[k] = P.Gd[DOF - 1][k] * vd[DOF - 1][k];
        if (j == DOF - 1) {
            MTRI(DOF - 1, j) = F[0] * P.w[DOF - 1][0] + F[1] * P.w[DOF - 1][1] + F[2] * P.w[DOF - 1][2]
                             + F[3] * P.v[DOF - 1][0] + F[4] * P.v[DOF - 1][1] + F[5] * P.v[DOF - 1][2];
        } else {
            MTRI(DOF - 1, j) = F[0] * P.w[DOF - 1][0] + F[1] * P.w[DOF - 1][1] + F[2] * P.w[DOF - 1][2]
                             + F[3] * P.v[DOF - 1][0] + F[4] * P.v[DOF - 1][1] + F[5] * P.v[DOF - 1][2];
#pragma unroll
            for (int ii = DOF - 2; ii >= 0; ii--) {
                if (ii < j) break;
                float X[6];
                adTF(Rj[ii + 1], Pj[ii + 1], F, X);
#pragma unroll
                for (int k = 0; k < 6; k++) F[k] = X[k] + P.Gd[ii][k] * vd[ii][k];
                MTRI(ii, j) = F[0] * P.w[ii][0] + F[1] * P.w[ii][1] + F[2] * P.w[ii][2]
                            + F[3] * P.v[ii][0] + F[4] * P.v[ii][1] + F[5] * P.v[ii][2];
            }
        }
    }

    // ---- LDL^T solve: M qacc = tau - bias (M SPD, lower triangle in Mtri) ----
    float x[DOF], invd[DOF];
#pragma unroll
    for (int i = 0; i < DOF; i++) x[i] = tq[i] - bias[i];
#pragma unroll
    for (int k = 0; k < DOF; k++) {
        float inv = __fdividef(1.0f, MTRI(k, k));
        invd[k] = inv;
        float fk[DOF];
#pragma unroll
        for (int i = k + 1; i < DOF; i++) fk[i] = MTRI(i, k) * inv;
#pragma unroll
        for (int i = k + 1; i < DOF; i++) {
            x[i] -= fk[i] * x[k];
#pragma unroll
            for (int jj = k + 1; jj <= i; jj++)
                MTRI(i, jj) -= fk[i] * MTRI(jj, k);
        }
#pragma unroll
        for (int i = k + 1; i < DOF; i++) MTRI(i, k) = fk[i];
    }
#pragma unroll
    for (int i = 0; i < DOF; i++) x[i] *= invd[i];
#pragma unroll
    for (int i = DOF - 2; i >= 0; i--) {
        float s = x[i];
#pragma unroll
        for (int jj = i + 1; jj < DOF; jj++) s -= MTRI(jj, i) * x[jj];
        x[i] = s;
    }
#pragma unroll
    for (int i = 0; i < DOF; i++) qacc[i] = x[i];
}

// ---------------------------------------------------------------------------
// Main kernel: one thread per batch element; RK4 + wrap/clip + FK.
// ---------------------------------------------------------------------------
__global__ void __launch_bounds__(NTHREADS)
arm_kernel(const float* __restrict__ state, const float* __restrict__ action,
           const float* __restrict__ gravity, float* __restrict__ out) {
    __shared__ Params sp;
    {
        const float* src = reinterpret_cast<const float*>(&g_params);
        float* dst = reinterpret_cast<float*>(&sp);
        for (int idx = threadIdx.x; idx < (int)(sizeof(Params) / 4); idx += NTHREADS)
            dst[idx] = src[idx];
    }
    __syncthreads();

    int b = blockIdx.x * NTHREADS + threadIdx.x;

    float q0[DOF], dq0[DOF], tq[DOF], g[3];
#pragma unroll
    for (int i = 0; i < DOF; i++) {
        q0[i]  = state[b * 14 + i];
        dq0[i] = state[b * 14 + DOF + i];
        tq[i]  = action[b * DOF + i] * ACTION_RANGE;
    }
    g[0] = gravity[0]; g[1] = gravity[1]; g[2] = gravity[2];

    const float h = TSTEP;
    float qs[DOF], dqs[DOF], qc[DOF], dqc[DOF];
#pragma unroll
    for (int i = 0; i < DOF; i++) { qc[i] = q0[i]; dqc[i] = dq0[i]; qs[i] = 0.f; dqs[i] = 0.f; }

#pragma unroll 1
    for (int st = 0; st < 4; st++) {
        float qacc[DOF];
        compute_qacc(sp, qc, dqc, tq, g, qacc);
        float wk = (st == 1 || st == 2) ? 2.0f : 1.0f;
        float cc = (st == 2) ? 1.0f : 0.5f;
#pragma unroll
        for (int i = 0; i < DOF; i++) {
            qs[i]  += wk * dqc[i];
            dqs[i] += wk * qacc[i];
            qc[i]  = q0[i]  + cc * h * dqc[i];
            dqc[i] = dq0[i] + cc * h * qacc[i];
        }
    }

    const float PI = 3.14159265358979323846f;
    const float TWO_PI = 6.28318530717958647692f;
    float qn[DOF];
#pragma unroll
    for (int i = 0; i < DOF; i++) {
        float qv = q0[i] + (h / 6.0f) * qs[i];
        float t = fmodf(qv + PI, TWO_PI);
        if (t < 0.0f) t += TWO_PI;
        qn[i] = t - PI;
        float dv = dq0[i] + (h / 6.0f) * dqs[i];
        dv = fminf(fmaxf(dv, -MAX_VEL), MAX_VEL);
        out[b * 14 + i] = qn[i];
        out[b * 14 + DOF + i] = dv;
    }

    // ---- FK: end-effector (x, y). Only rows 0,1 of T are tracked. ----
    float TR[6] = { 1, 0, 0, 0, 1, 0 };   // rows 0,1 of R
    float Tp[2] = { 0, 0 };
#pragma unroll
    for (int i = 0; i < DOF; i++) {
        float s, c;
        __sincosf(qn[i], &s, &c);
        const float* w = sp.w[i];
        const float* v = sp.v[i];
        float omc = 1.0f - c;
        float Re[9];
        Re[0] = c + omc * w[0] * w[0];
        Re[1] = s * (-w[2]) + omc * w[0] * w[1];
        Re[2] = s * ( w[1]) + omc * w[0] * w[2];
        Re[3] = s * ( w[2]) + omc * w[1] * w[0];
        Re[4] = c + omc * w[1] * w[1];
        Re[5] = s * (-w[0]) + omc * w[1] * w[2];
        Re[6] = s * (-w[1]) + omc * w[2] * w[0];
        Re[7] = s * ( w[0]) + omc * w[2] * w[1];
        Re[8] = c + omc * w[2] * w[2];
        float th = qn[i];
        float tms = th - s;
        float pe[3];
#pragma unroll
        for (int k = 0; k < 3; k++)
            pe[k] = th * v[k] + omc * sp.wxv[i][k] + tms * (w[k] * sp.wdv[i] - v[k]);
        const float* Mr = sp.Mr[i];
        const float* Mp = sp.Mp[i];
        // Tm = TR(2x3) * Mr(3x3)
        float Tm[6];
#pragma unroll
        for (int r = 0; r < 2; r++)
#pragma unroll
            for (int cc = 0; cc < 3; cc++)
                Tm[r * 3 + cc] = TR[r * 3 + 0] * Mr[0 * 3 + cc]
                               + TR[r * 3 + 1] * Mr[1 * 3 + cc]
                               + TR[r * 3 + 2] * Mr[2 * 3 + cc];
        // Tp += TR * Mp ; then TR = Tm * Re ; Tp += Tm * pe
        float nTR[6], nTp[2];
#pragma unroll
        for (int r = 0; r < 2; r++) {
            nTp[r] = Tp[r]
                   + TR[r * 3 + 0] * Mp[0] + TR[r * 3 + 1] * Mp[1] + TR[r * 3 + 2] * Mp[2]
                   + Tm[r * 3 + 0] * pe[0] + Tm[r * 3 + 1] * pe[1] + Tm[r * 3 + 2] * pe[2];
#pragma unroll
            for (int cc = 0; cc < 3; cc++)
                nTR[r * 3 + cc] = Tm[r * 3 + 0] * Re[0 * 3 + cc]
                                + Tm[r * 3 + 1] * Re[1 * 3 + cc]
                                + Tm[r * 3 + 2] * Re[2 * 3 + cc];
        }
#pragma unroll
        for (int k = 0; k < 6; k++) TR[k] = nTR[k];
        Tp[0] = nTp[0]; Tp[1] = nTp[1];
    }
    const float* Mp7 = sp.Mp[DOF];
    float ex = TR[0] * Mp7[0] + TR[1] * Mp7[1] + TR[2] * Mp7[2] + Tp[0];
    float ey = TR[3] * Mp7[0] + TR[4] * Mp7[1] + TR[5] * Mp7[2] + Tp[1];
    out[BATCH * 14 + b * 2 + 0] = ex;
    out[BATCH * 14 + b * 2 + 1] = ey;
}

extern "C" void kernel_launch(void* const* d_in, const int* in_sizes, int n_in,
                              void* d_out, int out_size) {
    const float* state   = (const float*)d_in[0];
    const float* action  = (const float*)d_in[1];
    const float* M_      = (const float*)d_in[2];
    const float* A_      = (const float*)d_in[3];
    const float* G_      = (const float*)d_in[4];
    const float* gravity = (const float*)d_in[5];
    float* out = (float*)d_out;

    setup_kernel<<<1, 32>>>(M_, A_, G_);
    arm_kernel<<<BATCH / NTHREADS, NTHREADS>>>(state, action, gravity, out);
}